// round 5
// baseline (speedup 1.0000x reference)
#include <cuda_runtime.h>
#include <cstdint>

#define KM 1024
#define KN 50000
#define CAP 1024
#define LAMBDA 320.0f
#define NQ 12500            // KN/4
#define NQ_PAD 12544        // 49*256: uniform trip count for warp-sync ops

// ---------------- device scratch (static; no allocations) ----------------
__device__ float g_logp[KN];
__device__ __align__(16) unsigned g_th[KN];   // integer bits threshold
__device__ float g_rowsum[KM];

// ---------------- threefry2x32 with key (0, 42), partitionable fold ----------------
__device__ __forceinline__ void tf_round(unsigned &a, unsigned &b, int r) {
    a += b;
    b = __funnelshift_l(b, b, r);
    b ^= a;
}

__device__ __forceinline__ unsigned tf_bits(unsigned L) {
    const unsigned ks0 = 0u, ks1 = 42u, ks2 = 0x1BD11BF0u;
    unsigned x0 = ks0;
    unsigned x1 = L + ks1;
    tf_round(x0,x1,13); tf_round(x0,x1,15); tf_round(x0,x1,26); tf_round(x0,x1,6);
    x0 += ks1; x1 += ks2 + 1u;
    tf_round(x0,x1,17); tf_round(x0,x1,29); tf_round(x0,x1,16); tf_round(x0,x1,24);
    x0 += ks2; x1 += ks0 + 2u;
    tf_round(x0,x1,13); tf_round(x0,x1,15); tf_round(x0,x1,26); tf_round(x0,x1,6);
    x0 += ks0; x1 += ks1 + 3u;
    tf_round(x0,x1,17); tf_round(x0,x1,29); tf_round(x0,x1,16); tf_round(x0,x1,24);
    x0 += ks1; x1 += ks2 + 4u;
    tf_round(x0,x1,13); tf_round(x0,x1,15); tf_round(x0,x1,26); tf_round(x0,x1,6);
    x0 += ks2; x1 += ks0 + 5u;
    return x0 ^ x1;
}

__device__ __forceinline__ float logsig(float x) {
    float z = -fabsf(x);
    float l = log1pf(expf(z));
    return (x >= 0.f) ? -l : (x - l);
}

// ---------------- kernel 0: per-column tables ----------------
__global__ void k_setup(const float* __restrict__ noise) {
    int j = blockIdx.x * blockDim.x + threadIdx.x;
    if (j < KN) {
        float p = noise[j];
        g_logp[j] = logf(p);
        // keeps a strict superset of {score >= -log(LAMBDA)}; E[count]=LAMBDA/row
        float uth = expf(-LAMBDA * p) * 0.999f;
        unsigned m = __float_as_uint(1.0f + uth) & 0x7FFFFFu;
        unsigned th = m << 9;
        g_th[j] = (th > 4096u) ? th - 4096u : 0u;
    }
}

// ---------------- fused: threefry scan + exact radix top-k + row loss ----------------
__global__ __launch_bounds__(256, 8) void k_main(const float* __restrict__ outp,
                                                 const float* __restrict__ tgt,
                                                 const int* __restrict__ pneg) {
    __shared__ unsigned long long sk[CAP];
    __shared__ unsigned int hist[256];
    __shared__ int s_cnt, s_bin, s_rem, s_done, s_np;
    __shared__ float s_f[8];
    __shared__ int   s_i[8];

    const int r    = blockIdx.x;
    const int tid  = threadIdx.x;
    const int lane = tid & 31;
    if (tid == 0) s_cnt = 0;
    __syncthreads();

    const float4* t4 = (const float4*)(tgt + (size_t)r * KN);
    const uint4*  h4 = (const uint4*)g_th;
    const unsigned base = (unsigned)r * (unsigned)KN;

    float s1 = 0.f;
    int   np = 0;

    // padded strided loop: every lane of every warp runs the same trip count,
    // so ballot/shfl with full masks are legal on the ragged tail.
    for (int q = tid; q < NQ_PAD; q += 256) {
        const bool valid = (q < NQ);
        float4 tv4 = valid ? t4[q] : make_float4(0.f, 0.f, 0.f, 0.f);
        uint4  th4 = valid ? h4[q] : make_uint4(0u, 0u, 0u, 0u);
        float    tv[4] = {tv4.x, tv4.y, tv4.z, tv4.w};
        unsigned th[4] = {th4.x, th4.y, th4.z, th4.w};
        unsigned j0 = (unsigned)q * 4u;
        #pragma unroll
        for (int e = 0; e < 4; e++) {
            unsigned j = j0 + (unsigned)e;
            unsigned bits = tf_bits(base + j);
            bool cand = valid && (bits >= th[e]);
            unsigned cm = __ballot_sync(0xFFFFFFFFu, cand);
            if (cm) {                              // warp-uniform; ~18.5% of elems
                int ldr = __ffs((int)cm) - 1;
                int sbase = 0;
                if (lane == ldr) sbase = atomicAdd(&s_cnt, __popc(cm));
                sbase = __shfl_sync(0xFFFFFFFFu, sbase, ldr);
                if (cand) {
                    int slot = sbase + __popc(cm & ((1u << lane) - 1u));
                    if (slot < CAP)
                        sk[slot] = ((unsigned long long)bits << 32) | j;
                }
            }
            bool pos = (tv[e] != 0.0f);
            unsigned pm = __ballot_sync(0xFFFFFFFFu, pos);
            if (pm) {                              // warp-uniform; ~0.64% of elems
                if (pos) {
                    np++;
                    s1 += tv[e] * logsig(outp[(size_t)r * KN + j]);
                }
            }
        }
    }

    // block reduce s1 / np
    #pragma unroll
    for (int off = 16; off; off >>= 1) {
        s1 += __shfl_down_sync(0xFFFFFFFFu, s1, off);
        np += __shfl_down_sync(0xFFFFFFFFu, np, off);
    }
    if (lane == 0) { s_f[tid >> 5] = s1; s_i[tid >> 5] = np; }
    __syncthreads();
    if (tid == 0) {
        float a = 0.f; int b = 0;
        #pragma unroll
        for (int i = 0; i < 8; i++) { a += s_f[i]; b += s_i[i]; }
        s_f[0] = a;            // s1 total
        s_np   = b;
    }
    __syncthreads();

    int c = s_cnt; if (c > CAP) c = CAP;
    int k = s_np * pneg[0]; if (k > KN) k = KN;
    int sel = (k < c) ? k : c;

    float s2 = 0.f;
    if (sel > 0) {
        // convert raw (bits, j) -> sortable key in place
        for (int i = tid; i < c; i += 256) {
            unsigned long long raw = sk[i];
            unsigned bits = (unsigned)(raw >> 32);
            unsigned j    = (unsigned)(raw & 0xFFFFFFFFull);
            float u = __uint_as_float((bits >> 9) | 0x3F800000u) - 1.0f;
            u = fmaxf(u, 1.17549435e-38f);
            float g = -logf(-logf(u));
            float s = g_logp[j] + g;
            unsigned sb = __float_as_uint(s);
            sb = (sb & 0x80000000u) ? ~sb : (sb | 0x80000000u);
            sk[i] = ((unsigned long long)sb << 32) | (0xFFFFFFFFu - j);
        }
        if (tid == 0) { s_rem = sel; s_done = 0; }
        __syncthreads();

        unsigned long long prefix = 0ull;
        for (int shift = 56; shift >= 0 && !s_done; shift -= 8) {
            hist[tid] = 0;
            __syncthreads();
            unsigned long long mask = (shift == 56) ? 0ull : (~0ull << (shift + 8));
            for (int i = tid; i < c; i += 256) {
                unsigned long long key = sk[i];
                if ((key & mask) == prefix)
                    atomicAdd(&hist[(unsigned)(key >> shift) & 0xFFu], 1u);
            }
            __syncthreads();
            if (tid == 0) {
                int rem = s_rem, cum = 0, b = 255;
                for (;; b--) {
                    int h = (int)hist[b];
                    if (cum + h >= rem || b == 0) {
                        s_bin = b; s_rem = rem - cum;
                        if (h == rem - cum) s_done = 1;   // bin fully selected
                        break;
                    }
                    cum += h;
                }
            }
            __syncthreads();
            prefix |= ((unsigned long long)(unsigned)s_bin) << shift;
        }
        // keys unique => exactly `sel` keys >= prefix
        for (int i = tid; i < c; i += 256) {
            unsigned long long key = sk[i];
            if (key >= prefix) {
                unsigned idx = 0xFFFFFFFFu - (unsigned)(key & 0xFFFFFFFFull);
                s2 += logsig(-outp[(size_t)r * KN + idx]);
            }
        }
    }

    #pragma unroll
    for (int off = 16; off; off >>= 1)
        s2 += __shfl_down_sync(0xFFFFFFFFu, s2, off);
    __syncthreads();                 // s_f[0] holds s1 total; protect reuse below
    if (lane == 0) s_i[tid >> 5] = __float_as_int(s2);
    __syncthreads();
    if (tid == 0) {
        float tot = 0.f;
        #pragma unroll
        for (int i = 0; i < 8; i++) tot += __int_as_float(s_i[i]);
        g_rowsum[r] = s_f[0] + tot;
    }
}

// ---------------- final reduction ----------------
__global__ __launch_bounds__(256) void k_final(float* outv) {
    __shared__ float s_f[8];
    const int tid = threadIdx.x;
    float s = 0.f;
    for (int i = tid; i < KM; i += 256) s += g_rowsum[i];
    #pragma unroll
    for (int off = 16; off; off >>= 1)
        s += __shfl_down_sync(0xFFFFFFFFu, s, off);
    if ((tid & 31) == 0) s_f[tid >> 5] = s;
    __syncthreads();
    if (tid == 0) {
        float tot = 0.f;
        #pragma unroll
        for (int i = 0; i < 8; i++) tot += s_f[i];
        outv[0] = -(tot / (float)KM);
    }
}

// ---------------- launch ----------------
extern "C" void kernel_launch(void* const* d_in, const int* in_sizes, int n_in,
                              void* d_out, int out_size) {
    const float* outp  = (const float*)d_in[0];
    const float* tgt   = (const float*)d_in[1];
    const float* noise = (const float*)d_in[2];
    const int*   pneg  = (const int*)d_in[3];
    float* ov = (float*)d_out;

    k_setup<<<(KN + 255) / 256, 256>>>(noise);
    k_main<<<KM, 256>>>(outp, tgt, pneg);
    k_final<<<1, 256>>>(ov);
}